// round 4
// baseline (speedup 1.0000x reference)
#include <cuda_runtime.h>

// Problem constants (LatentCoulombLongRange: N=8192, F=128, H=64, B=8)
#define MAXN 8192
#define FDIM 128
#define HDIM 64
#define MAXB 64

// Scratch (allocation-free rule: __device__ globals; zero-initialized at load)
__device__ float  d_qraw[MAXN];
__device__ float4 d_qpos[MAXN];       // {x, y, z, centered q}
__device__ int    d_gstart[MAXB];
__device__ int    d_gend[MAXB];
__device__ float  d_gsum[MAXB];       // per-graph q sum (atomics); re-zeroed by pair_kernel

// ---- raw single-MUFU intrinsics (avoid non-fast-math slow paths) ----------
__device__ __forceinline__ float fast_rsqrt(float x) {
    float r; asm("rsqrt.approx.ftz.f32 %0, %1;" : "=f"(r) : "f"(x)); return r;
}
__device__ __forceinline__ float fast_ex2(float x) {
    float r; asm("ex2.approx.ftz.f32 %0, %1;" : "=f"(r) : "f"(x)); return r;
}
__device__ __forceinline__ float fast_rcp(float x) {
    float r; asm("rcp.approx.ftz.f32 %0, %1;" : "=f"(r) : "f"(x)); return r;
}

#define LOG2E 1.44269504088896f

// ---------------------------------------------------------------------------
// K1: charge-head MLP  q_raw[i] = (silu(x W1 + b1) W2 + b2)
//     One warp per atom, 4 atoms per 128-thread block, 2 hidden cols/thread.
//     Lane 0 also accumulates per-graph charge sum (atomicAdd over 8 addrs)
//     and detects sorted-batch segment boundaries.
// ---------------------------------------------------------------------------
__global__ void mlp_kernel(const float* __restrict__ x,
                           const float* __restrict__ W1,
                           const float* __restrict__ b1,
                           const float* __restrict__ W2,
                           const float* __restrict__ b2,
                           const int* __restrict__ batch,
                           int n) {
    int sub  = threadIdx.x >> 5;           // atom sub-index in block (0..3)
    int lane = threadIdx.x & 31;
    int i = blockIdx.x * 4 + sub;
    if (i >= n) return;

    __shared__ float sx[4][FDIM];

    // warp loads its atom's x row: 32 lanes x float4 = 128 floats
    ((float4*)sx[sub])[lane] = ((const float4*)(x + i * FDIM))[lane];
    __syncwarp();

    const float2* W1v = (const float2*)W1;     // [128][32] float2
    float2 acc = ((const float2*)b1)[lane];

#pragma unroll
    for (int f = 0; f < FDIM; f++) {
        float  xf = sx[sub][f];
        float2 w  = W1v[f * 32 + lane];
        acc.x = fmaf(xf, w.x, acc.x);
        acc.y = fmaf(xf, w.y, acc.y);
    }

    // SiLU (sigmoid via single EX2 + RCP) + W2 contraction
    float2 w2 = ((const float2*)W2)[lane];
    float s0 = acc.x * fast_rcp(1.0f + fast_ex2(-LOG2E * acc.x));
    float s1 = acc.y * fast_rcp(1.0f + fast_ex2(-LOG2E * acc.y));
    float v = fmaf(s0, w2.x, s1 * w2.y);

#pragma unroll
    for (int off = 16; off; off >>= 1)
        v += __shfl_down_sync(0xffffffffu, v, off);

    if (lane == 0) {
        float q = v + b2[0];
        d_qraw[i] = q;
        int g = batch[i];
        atomicAdd(&d_gsum[g], q);
        // sorted-batch segment boundaries
        if (i == 0     || batch[i - 1] != g) d_gstart[g] = i;
        if (i == n - 1 || batch[i + 1] != g) d_gend[g]   = i + 1;
    }
}

// ---------------------------------------------------------------------------
// K2: pack {pos, centered q} into float4. Mean computed inline from
//     d_gsum / (gend - gstart)  (no separate mean kernel).
// ---------------------------------------------------------------------------
__global__ void pack_kernel(const float* __restrict__ pos,
                            const int* __restrict__ batch, int n) {
    int i = blockIdx.x * blockDim.x + threadIdx.x;
    if (i < n) {
        int g = batch[i];
        float cnt  = (float)max(1, d_gend[g] - d_gstart[g]);
        float mean = d_gsum[g] / cnt;
        float qc = d_qraw[i] - mean;
        d_qpos[i] = make_float4(pos[3 * i], pos[3 * i + 1], pos[3 * i + 2], qc);
    }
}

// ---------------------------------------------------------------------------
// K3: screened Coulomb pair sum. One warp per atom i; lanes stride over the
//     atom's contiguous graph range [gs, ge), unrolled x4 for 4 independent
//     MUFU chains (raw RSQ/EX2, 2 MUFU per pair). Self-term included in the
//     loop and subtracted with the IDENTICAL sequence so error cancels.
//     Tail: block 0 re-zeroes d_gsum for the next graph replay.
// ---------------------------------------------------------------------------
__device__ __forceinline__ float pair_term(float4 pj, float4 pi,
                                           float soft2, float nscr_log2e,
                                           float& k_out) {
    float dx = pj.x - pi.x;
    float dy = pj.y - pi.y;
    float dz = pj.z - pi.z;
    float r2 = fmaf(dx, dx, fmaf(dy, dy, fmaf(dz, dz, soft2)));
    float rinv = fast_rsqrt(r2);
    float r = r2 * rinv;
    k_out = fast_ex2(nscr_log2e * r) * rinv;
    return pj.w;
}

__global__ void pair_kernel(const int* __restrict__ batch,
                            const float* __restrict__ scr_p,
                            const float* __restrict__ soft_p,
                            float* __restrict__ out, int n) {
    // reset per-graph accumulators for the next replay (values already consumed)
    if (blockIdx.x == 0 && threadIdx.x < MAXB) d_gsum[threadIdx.x] = 0.0f;

    int i    = (blockIdx.x * blockDim.x + threadIdx.x) >> 5;
    int lane = threadIdx.x & 31;
    if (i >= n) return;

    const float4* __restrict__ qp = d_qpos;

    float scr   = *scr_p;
    float soft  = *soft_p;
    float soft2 = soft * soft;
    const float nscr_log2e = -scr * LOG2E;

    int g  = batch[i];
    int gs = d_gstart[g];
    int ge = d_gend[g];

    float4 pi = qp[i];
    float acc = 0.0f;

    int jlast = ge - 1;
    for (int j0 = gs + lane; j0 < ge; j0 += 128) {
        int j1 = j0 + 32, j2 = j0 + 64, j3 = j0 + 96;
        float4 p0 = qp[min(j0, jlast)];
        float4 p1 = qp[min(j1, jlast)];
        float4 p2 = qp[min(j2, jlast)];
        float4 p3 = qp[min(j3, jlast)];
        float k0, k1, k2, k3;
        float q0 = pair_term(p0, pi, soft2, nscr_log2e, k0);
        float q1 = pair_term(p1, pi, soft2, nscr_log2e, k1);
        float q2 = pair_term(p2, pi, soft2, nscr_log2e, k2);
        float q3 = pair_term(p3, pi, soft2, nscr_log2e, k3);
        acc = fmaf(q0, k0, acc);                 // j0 < ge by loop condition
        if (j1 < ge) acc = fmaf(q1, k1, acc);
        if (j2 < ge) acc = fmaf(q2, k2, acc);
        if (j3 < ge) acc = fmaf(q3, k3, acc);
    }

    // subtract self-term computed with the same intrinsic sequence
    if (lane == 0) {
        float ks;
        float qs = pair_term(pi, pi, soft2, nscr_log2e, ks);
        acc -= qs * ks;
    }

#pragma unroll
    for (int off = 16; off; off >>= 1)
        acc += __shfl_down_sync(0xffffffffu, acc, off);

    if (lane == 0) out[i] = 0.5f * pi.w * acc;
}

// ---------------------------------------------------------------------------
// launch
// inputs: 0:x 1:pos 2:cell 3:W1 4:b1 5:W2 6:b2 7:screening 8:softening 9:batch
// ---------------------------------------------------------------------------
extern "C" void kernel_launch(void* const* d_in, const int* in_sizes, int n_in,
                              void* d_out, int out_size) {
    const float* x     = (const float*)d_in[0];
    const float* pos   = (const float*)d_in[1];
    const float* W1    = (const float*)d_in[3];
    const float* b1    = (const float*)d_in[4];
    const float* W2    = (const float*)d_in[5];
    const float* b2    = (const float*)d_in[6];
    const float* scr   = (const float*)d_in[7];
    const float* soft  = (const float*)d_in[8];
    const int*   batch = (const int*)d_in[9];
    float* out = (float*)d_out;

    int n = in_sizes[9];           // N atoms

    mlp_kernel<<<(n + 3) / 4, 128>>>(x, W1, b1, W2, b2, batch, n);
    pack_kernel<<<(n + 255) / 256, 256>>>(pos, batch, n);
    int threads = 256;
    int blocks  = (n * 32 + threads - 1) / threads;
    pair_kernel<<<blocks, threads>>>(batch, scr, soft, out, n);
}

// round 5
// speedup vs baseline: 1.9634x; 1.9634x over previous
#include <cuda_runtime.h>

// Problem constants (LatentCoulombLongRange: N=8192, F=128, H=64, B=8)
#define MAXN 8192
#define FDIM 128
#define HDIM 64
#define MAXB 64
#define NSLOT 32          // charge-sum slots per graph (atomic de-serialization)

// Scratch (allocation-free rule: __device__ globals; zero-initialized at load)
__device__ float  d_qraw[MAXN];
__device__ float4 d_qpos[MAXN];            // {x, y, z, centered q}
__device__ int    d_gstart[MAXB];
__device__ int    d_gend[MAXB];
__device__ float  d_gsum[MAXB * NSLOT];    // slotted per-graph q sums; re-zeroed by pair_kernel

// ---- raw single-MUFU intrinsics (avoid non-fast-math slow paths) ----------
__device__ __forceinline__ float fast_rsqrt(float x) {
    float r; asm("rsqrt.approx.ftz.f32 %0, %1;" : "=f"(r) : "f"(x)); return r;
}
__device__ __forceinline__ float fast_ex2(float x) {
    float r; asm("ex2.approx.ftz.f32 %0, %1;" : "=f"(r) : "f"(x)); return r;
}
__device__ __forceinline__ float fast_rcp(float x) {
    float r; asm("rcp.approx.ftz.f32 %0, %1;" : "=f"(r) : "f"(x)); return r;
}

#define LOG2E 1.44269504088896f

// ---------------------------------------------------------------------------
// K1: charge-head MLP  q_raw[i] = (silu(x W1 + b1) W2 + b2)
//     Block = 256 threads = 8 warps, 32 atoms/block; each warp computes 4
//     atoms so each W1 load (LDG.64, L1-hot) feeds 8 FFMAs. Per-graph charge
//     sums go to 32 slots/graph to avoid L2-atomic serialization.
// ---------------------------------------------------------------------------
__global__ void mlp_kernel(const float* __restrict__ x,
                           const float* __restrict__ W1,
                           const float* __restrict__ b1,
                           const float* __restrict__ W2,
                           const float* __restrict__ b2,
                           const int* __restrict__ batch,
                           int n) {
    int warp = threadIdx.x >> 5;           // 0..7
    int lane = threadIdx.x & 31;
    int base = blockIdx.x * 32;            // first atom of this block

    __shared__ float sx[32][FDIM];         // 16 KB

    // cooperative load of 32 x-rows: 1024 float4, 256 threads x 4
    const float4* xv = (const float4*)(x + (size_t)base * FDIM);
#pragma unroll
    for (int t = 0; t < 4; t++) {
        int idx = threadIdx.x + t * 256;   // 0..1023
        int row = idx >> 5;                // 32 float4 per row
        int col = idx & 31;
        ((float4*)sx[row])[col] = xv[idx];
    }
    __syncthreads();

    int a0 = warp * 4;                     // local atoms a0..a0+3
    const float2* W1v = (const float2*)W1; // [128][32] float2
    float2 bb = ((const float2*)b1)[lane];
    float2 acc0 = bb, acc1 = bb, acc2 = bb, acc3 = bb;

#pragma unroll
    for (int f = 0; f < FDIM; f++) {
        float2 w = W1v[f * 32 + lane];
        float x0 = sx[a0 + 0][f];
        float x1 = sx[a0 + 1][f];
        float x2 = sx[a0 + 2][f];
        float x3 = sx[a0 + 3][f];
        acc0.x = fmaf(x0, w.x, acc0.x);  acc0.y = fmaf(x0, w.y, acc0.y);
        acc1.x = fmaf(x1, w.x, acc1.x);  acc1.y = fmaf(x1, w.y, acc1.y);
        acc2.x = fmaf(x2, w.x, acc2.x);  acc2.y = fmaf(x2, w.y, acc2.y);
        acc3.x = fmaf(x3, w.x, acc3.x);  acc3.y = fmaf(x3, w.y, acc3.y);
    }

    // SiLU + W2 contraction, then 4 warp reductions
    float2 w2 = ((const float2*)W2)[lane];
    float q[4];
#pragma unroll
    for (int a = 0; a < 4; a++) {
        float2 acc = (a == 0) ? acc0 : (a == 1) ? acc1 : (a == 2) ? acc2 : acc3;
        float s0 = acc.x * fast_rcp(1.0f + fast_ex2(-LOG2E * acc.x));
        float s1 = acc.y * fast_rcp(1.0f + fast_ex2(-LOG2E * acc.y));
        float v = fmaf(s0, w2.x, s1 * w2.y);
#pragma unroll
        for (int off = 16; off; off >>= 1)
            v += __shfl_down_sync(0xffffffffu, v, off);
        q[a] = v;                          // valid in lane 0
    }

    if (lane == 0) {
        float bias = b2[0];
#pragma unroll
        for (int a = 0; a < 4; a++) {
            int i = base + a0 + a;
            if (i >= n) break;
            float qi = q[a] + bias;
            d_qraw[i] = qi;
            int g = batch[i];
            atomicAdd(&d_gsum[g * NSLOT + (i & (NSLOT - 1))], qi);
            // sorted-batch segment boundaries
            if (i == 0     || batch[i - 1] != g) d_gstart[g] = i;
            if (i == n - 1 || batch[i + 1] != g) d_gend[g]   = i + 1;
        }
    }
}

// ---------------------------------------------------------------------------
// K2: pack {pos, centered q} into float4. Per-graph mean reduced from the
//     slotted sums into SMEM at block start (no separate mean kernel).
// ---------------------------------------------------------------------------
__global__ void pack_kernel(const float* __restrict__ pos,
                            const int* __restrict__ batch, int n, int nb) {
    __shared__ float smean[MAXB];
    int t = threadIdx.x;                   // 256 threads
    if (t < MAXB) smean[t] = 0.0f;
    __syncthreads();
    for (int s = t; s < nb * NSLOT; s += 256)
        atomicAdd(&smean[s / NSLOT], d_gsum[s]);
    __syncthreads();

    int i = blockIdx.x * 256 + t;
    if (i < n) {
        int g = batch[i];
        float cnt  = (float)max(1, d_gend[g] - d_gstart[g]);
        float mean = smean[g] / cnt;
        float qc = d_qraw[i] - mean;
        d_qpos[i] = make_float4(pos[3 * i], pos[3 * i + 1], pos[3 * i + 2], qc);
    }
}

// ---------------------------------------------------------------------------
// K3: screened Coulomb pair sum. One warp per atom i; lanes stride over the
//     atom's contiguous graph range [gs, ge), unrolled x4 for 4 independent
//     MUFU chains (raw RSQ/EX2: 2 MUFU per pair). Self-term included in the
//     loop and subtracted with the IDENTICAL sequence so error cancels.
//     Tail duty: block 0 re-zeroes d_gsum for the next graph replay.
// ---------------------------------------------------------------------------
__device__ __forceinline__ float pair_term(float4 pj, float4 pi,
                                           float soft2, float nscr_log2e,
                                           float& k_out) {
    float dx = pj.x - pi.x;
    float dy = pj.y - pi.y;
    float dz = pj.z - pi.z;
    float r2 = fmaf(dx, dx, fmaf(dy, dy, fmaf(dz, dz, soft2)));
    float rinv = fast_rsqrt(r2);
    float r = r2 * rinv;
    k_out = fast_ex2(nscr_log2e * r) * rinv;
    return pj.w;
}

__global__ void pair_kernel(const int* __restrict__ batch,
                            const float* __restrict__ scr_p,
                            const float* __restrict__ soft_p,
                            float* __restrict__ out, int n) {
    // reset slotted accumulators for the next replay (values already consumed)
    if (blockIdx.x == 0) {
#pragma unroll
        for (int s = threadIdx.x; s < MAXB * NSLOT; s += 256)
            d_gsum[s] = 0.0f;
    }

    int i    = (blockIdx.x * blockDim.x + threadIdx.x) >> 5;
    int lane = threadIdx.x & 31;
    if (i >= n) return;

    const float4* __restrict__ qp = d_qpos;

    float scr   = *scr_p;
    float soft  = *soft_p;
    float soft2 = soft * soft;
    const float nscr_log2e = -scr * LOG2E;

    int g  = batch[i];
    int gs = d_gstart[g];
    int ge = d_gend[g];

    float4 pi = qp[i];
    float acc = 0.0f;

    int jlast = ge - 1;
    for (int j0 = gs + lane; j0 < ge; j0 += 128) {
        int j1 = j0 + 32, j2 = j0 + 64, j3 = j0 + 96;
        float4 p0 = qp[min(j0, jlast)];
        float4 p1 = qp[min(j1, jlast)];
        float4 p2 = qp[min(j2, jlast)];
        float4 p3 = qp[min(j3, jlast)];
        float k0, k1, k2, k3;
        float q0 = pair_term(p0, pi, soft2, nscr_log2e, k0);
        float q1 = pair_term(p1, pi, soft2, nscr_log2e, k1);
        float q2 = pair_term(p2, pi, soft2, nscr_log2e, k2);
        float q3 = pair_term(p3, pi, soft2, nscr_log2e, k3);
        acc = fmaf(q0, k0, acc);                 // j0 < ge by loop condition
        if (j1 < ge) acc = fmaf(q1, k1, acc);
        if (j2 < ge) acc = fmaf(q2, k2, acc);
        if (j3 < ge) acc = fmaf(q3, k3, acc);
    }

    // subtract self-term computed with the same intrinsic sequence
    if (lane == 0) {
        float ks;
        float qs = pair_term(pi, pi, soft2, nscr_log2e, ks);
        acc -= qs * ks;
    }

#pragma unroll
    for (int off = 16; off; off >>= 1)
        acc += __shfl_down_sync(0xffffffffu, acc, off);

    if (lane == 0) out[i] = 0.5f * pi.w * acc;
}

// ---------------------------------------------------------------------------
// launch
// inputs: 0:x 1:pos 2:cell 3:W1 4:b1 5:W2 6:b2 7:screening 8:softening 9:batch
// ---------------------------------------------------------------------------
extern "C" void kernel_launch(void* const* d_in, const int* in_sizes, int n_in,
                              void* d_out, int out_size) {
    const float* x     = (const float*)d_in[0];
    const float* pos   = (const float*)d_in[1];
    const float* W1    = (const float*)d_in[3];
    const float* b1    = (const float*)d_in[4];
    const float* W2    = (const float*)d_in[5];
    const float* b2    = (const float*)d_in[6];
    const float* scr   = (const float*)d_in[7];
    const float* soft  = (const float*)d_in[8];
    const int*   batch = (const int*)d_in[9];
    float* out = (float*)d_out;

    int n  = in_sizes[9];          // N atoms
    int nb = in_sizes[2] / 9;      // B graphs (cell is [B,3,3])
    if (nb > MAXB) nb = MAXB;

    mlp_kernel<<<(n + 31) / 32, 256>>>(x, W1, b1, W2, b2, batch, n);
    pack_kernel<<<(n + 255) / 256, 256>>>(pos, batch, n, nb);
    int threads = 256;
    int blocks  = (n * 32 + threads - 1) / threads;
    pair_kernel<<<blocks, threads>>>(batch, scr, soft, out, n);
}